// round 16
// baseline (speedup 1.0000x reference)
#include <cuda_runtime.h>
#include <cuda_bf16.h>
#include <stdint.h>

#define BB 8
#define NN 128
#define TT 8
#define LL 6
#define PP 1024
#define DD 256
#define NLABEL 40
#define BLP (BB*LL*PP)      /* 49152 */
#define M0C (1.0f/0.07f)
#define C2LOG (20.609929155556620f)   /* M0C * log2(e) */

/* ------------- device scratch (no allocations allowed) ------------- */
__device__ uint4 g_wh4[(size_t)BB*LL*PP*DD/8];  /* bf16 normalized rows */
__device__ int   g_K[BB];
__device__ int   g_gate[BB];
__device__ int   g_comp2orig[BB*PP];
__device__ int   g_orig2comp[BB*PP];
__device__ __align__(16) int g_clab[BB*PP];     /* labels by compact idx, pad=-1 */
__device__ int   g_cnegcnt[BB*PP];
__device__ int   g_poscnt_orig[BB*PP];
__device__ int   g_posingrp[BB*PP];
__device__ int   g_grpoff[BB*(NLABEL+1)];
__device__ int   g_grpitems[BB*PP];
__device__ int   g_idxlast_orig[BB*PP];         /* keyed by compact idx (k<K) */
__device__ __align__(16) int g_lastcomp[BB*PP]; /* compact last-neg idx, pad=-1 */
__device__ __align__(16) int g_pospick[BLP];    /* compact pick idx, pad=-1 */
__device__ float g_zp[BLP];
__device__ float g_zl[BLP];
__device__ float g_S[BLP];
__device__ float g_partial[BB*LL];
__device__ int   g_wl[BB*LL*16];
__device__ int   g_nwork;
__device__ int   g_witem;
__device__ int   g_fin;
__device__ int   g_done;

/* ------------------- helpers ------------------- */
__device__ __forceinline__ uint32_t rotl32(uint32_t x, int r) {
    return (x << r) | (x >> (32 - r));
}

/* JAX threefry2x32 with key = jax.random.key(42) -> (0, 42) */
__device__ __forceinline__ void threefry_0_42(uint32_t& x0, uint32_t& x1) {
    const uint32_t ks0 = 0u, ks1 = 42u, ks2 = 0u ^ 42u ^ 0x1BD11BDAu;
    x0 += ks0; x1 += ks1;
#define TF_RND(r) { x0 += x1; x1 = rotl32(x1, r); x1 ^= x0; }
    TF_RND(13) TF_RND(15) TF_RND(26) TF_RND(6)  x0 += ks1; x1 += ks2 + 1u;
    TF_RND(17) TF_RND(29) TF_RND(16) TF_RND(24) x0 += ks2; x1 += ks0 + 2u;
    TF_RND(13) TF_RND(15) TF_RND(26) TF_RND(6)  x0 += ks0; x1 += ks1 + 3u;
    TF_RND(17) TF_RND(29) TF_RND(16) TF_RND(24) x0 += ks1; x1 += ks2 + 4u;
    TF_RND(13) TF_RND(15) TF_RND(26) TF_RND(6)  x0 += ks2; x1 += ks0 + 5u;
#undef TF_RND
}

__device__ __forceinline__ void mma_bf16(float& d0, float& d1, float& d2, float& d3,
                                         uint32_t a0, uint32_t a1, uint32_t a2, uint32_t a3,
                                         uint32_t b0, uint32_t b1) {
    asm volatile(
        "mma.sync.aligned.m16n8k16.row.col.f32.bf16.bf16.f32 "
        "{%0,%1,%2,%3}, {%4,%5,%6,%7}, {%8,%9}, {%0,%1,%2,%3};"
        : "+f"(d0), "+f"(d1), "+f"(d2), "+f"(d3)
        : "r"(a0), "r"(a1), "r"(a2), "r"(a3), "r"(b0), "r"(b1));
}

#define LDSM4(r0, r1, r2, r3, addr) \
    asm volatile("ldmatrix.sync.aligned.m8n8.x4.shared.b16 {%0,%1,%2,%3}, [%4];" \
                 : "=r"(r0), "=r"(r1), "=r"(r2), "=r"(r3) : "r"(addr))

__device__ __forceinline__ void cp16(uint32_t dst, const void* src) {
    asm volatile("cp.async.cg.shared.global [%0], [%1], 16;" :: "r"(dst), "l"(src) : "memory");
}
#define CP_COMMIT() asm volatile("cp.async.commit_group;" ::: "memory")
#define CP_WAIT2()  asm volatile("cp.async.wait_group 2;" ::: "memory")

__device__ __forceinline__ uint32_t smem_u32(const void* p) {
    uint32_t a;
    asm("{ .reg .u64 t; cvta.to.shared.u64 t, %1; cvt.u32.u64 %0, t; }" : "=r"(a) : "l"(p));
    return a;
}

/* ------------------- K1: per-batch metadata (warp-scan ranks) ------------------- */
__global__ void k_meta(const int* __restrict__ thing, const int* __restrict__ label) {
    int b = blockIdx.x, tid = threadIdx.x;
    int wid = tid >> 5, lane = tid & 31;
    __shared__ int s_pack[PP];          /* 0 = invalid, else label+1 */
    __shared__ int s_cnt[NLABEL];
    __shared__ int s_off[NLABEL + 1];
    __shared__ int s_run[NLABEL];
    __shared__ int s_whist[8][NLABEL];
    __shared__ int s_wvalid[8];
    __shared__ int s_L1, s_L2, s_labL1, s_gate, s_K, s_crun;
    if (tid < NLABEL) { s_cnt[tid] = 0; s_run[tid] = 0; }
    if (tid == 0) { s_L1 = -1; s_L2 = -1; s_gate = 0; s_crun = 0; }
    if (b == 0 && tid == 0) { g_done = 0; g_witem = 0; g_fin = 0; }
    if (tid < LL) g_partial[b * LL + tid] = 0.f;
    __syncthreads();
    for (int p = tid; p < PP; p += blockDim.x) {
        int v = thing[b * PP + p];
        int lab = label[b * PP + p];
        s_pack[p] = (v != 0) ? (lab + 1) : 0;
        if (v != 0) { atomicAdd(&s_cnt[lab], 1); atomicMax(&s_L1, p); }
    }
    for (int n = tid; n < NN; n += blockDim.x) {
        int ss = 0;
        for (int t = 0; t < TT; t++) ss += thing[(b * NN + n) * TT + t];
        if (ss > 0) atomicAdd(&s_gate, 1);
    }
    __syncthreads();
    if (tid == 0) {
        int acc = 0;
        for (int v = 0; v < NLABEL; v++) { s_off[v] = acc; acc += s_cnt[v]; }
        s_off[NLABEL] = acc; s_K = acc;
        g_K[b] = acc;
        g_gate[b] = (s_gate >= 2) ? 1 : 0;
        s_labL1 = (s_L1 >= 0) ? (s_pack[s_L1] - 1) : -1;
    }
    __syncthreads();
    int labL1 = s_labL1;
    for (int p = tid; p < PP; p += blockDim.x) {
        int pk = s_pack[p];
        if (pk != 0 && (pk - 1) != labL1) atomicMax(&s_L2, p);
    }
    __syncthreads();
    int K = s_K, L1 = s_L1, L2 = s_L2;

    /* ranks via 4 chunks of 256, warp-scan within chunk (ballot + match_any) */
    uint32_t lmlt = (1u << lane) - 1u;
    for (int c = 0; c < 4; c++) {
        for (int i = tid; i < 8 * NLABEL; i += 256) s_whist[i / NLABEL][i % NLABEL] = 0;
        __syncthreads();

        int p = c * 256 + tid;
        int pk = s_pack[p];
        bool valid = (pk != 0);
        int lab = pk - 1;
        uint32_t vb = __ballot_sync(0xffffffffu, valid);
        uint32_t mm = __match_any_sync(0xffffffffu, pk);
        int crw = __popc(vb & lmlt);
        int grw = __popc(mm & lmlt);
        int leader = __ffs(mm) - 1;
        if (valid && lane == leader) s_whist[wid][lab] = __popc(mm);
        if (lane == 0) s_wvalid[wid] = __popc(vb);
        __syncthreads();

        if (valid) {
            int crk = crw, grk = grw;
            for (int w2 = 0; w2 < wid; w2++) {
                crk += s_wvalid[w2];
                grk += s_whist[w2][lab];
            }
            int crank = s_crun + crk;
            int grank = s_run[lab] + grk;
            g_orig2comp[b * PP + p] = crank;
            g_comp2orig[b * PP + crank] = p;
            g_clab[b * PP + crank] = lab;
            int cl = s_cnt[lab];
            g_poscnt_orig[b * PP + p] = cl - 1;
            g_cnegcnt[b * PP + crank] = K - cl;
            g_posingrp[b * PP + p] = grank;
            g_grpitems[b * PP + s_off[lab] + grank] = p;
            g_idxlast_orig[b * PP + crank] = (lab != labL1) ? L1 : L2;
        } else {
            g_orig2comp[b * PP + p] = -1;
        }
        __syncthreads();
        if (tid < NLABEL) {
            int t = 0;
            for (int w2 = 0; w2 < 8; w2++) t += s_whist[w2][tid];
            s_run[tid] += t;
        }
        if (tid == 0) {
            int t = 0;
            for (int w2 = 0; w2 < 8; w2++) t += s_wvalid[w2];
            s_crun += t;
        }
        __syncthreads();
    }

    if (tid <= NLABEL) g_grpoff[b * (NLABEL + 1) + tid] = s_off[tid];

    /* pad sentinels + compact last-neg index */
    for (int k = tid; k < PP; k += 256) {
        if (k < K) {
            int lo = g_idxlast_orig[b * PP + k];
            g_lastcomp[b * PP + k] = (lo >= 0) ? g_orig2comp[b * PP + lo] : -1;
        } else {
            g_lastcomp[b * PP + k] = -1;
            g_clab[b * PP + k] = -1;
            g_cnegcnt[b * PP + k] = 0;
        }
    }
    /* zero S + pad picks */
    for (int idx = tid; idx < LL * PP; idx += 256) {
        int l = idx >> 10, k = idx & 1023;
        g_S[((size_t)b * LL + l) * PP + k] = 0.f;
        if (k >= K) g_pospick[(b * LL + l) * PP + k] = -1;
    }
}

/* ------------- K2: fused norm (blocks < NORMG) + pick/worklist (blocks >= NORMG) ------------- */
#define NORMG 6144
__global__ void k_normpick(const float* __restrict__ meta, const int* __restrict__ label) {
    if (blockIdx.x < NORMG) {
        int w = (blockIdx.x * blockDim.x + threadIdx.x) >> 5;
        int lane = threadIdx.x & 31;
        int b = w / (LL * PP); int rem = w % (LL * PP);
        int l = rem / PP; int k = rem % PP;
        int K = g_K[b];
        int PPpad = ((K + 127) >> 7) << 7;
        if (k >= PPpad) return;
        size_t rowbase = ((size_t)(b * LL + l) * PP + k) * (DD / 8);
        if (k >= K) {
            g_wh4[rowbase + lane] = make_uint4(0u, 0u, 0u, 0u);
            return;
        }
        int p = g_comp2orig[b * PP + k];
        int n = p >> 3, t = p & 7;
        const float* src = meta + ((((size_t)b * NN + n) * TT + t) * LL + l) * DD;
        float4 v0 = ((const float4*)src)[lane * 2];
        float4 v1 = ((const float4*)src)[lane * 2 + 1];
        float ss = v0.x*v0.x + v0.y*v0.y + v0.z*v0.z + v0.w*v0.w
                 + v1.x*v1.x + v1.y*v1.y + v1.z*v1.z + v1.w*v1.w;
        for (int off = 16; off; off >>= 1) ss += __shfl_xor_sync(0xffffffffu, ss, off);
        float inv = 1.0f / fmaxf(sqrtf(ss), 1e-12f);
        v0.x*=inv; v0.y*=inv; v0.z*=inv; v0.w*=inv;
        v1.x*=inv; v1.y*=inv; v1.z*=inv; v1.w*=inv;
        __nv_bfloat162 h0 = __floats2bfloat162_rn(v0.x, v0.y);
        __nv_bfloat162 h1 = __floats2bfloat162_rn(v0.z, v0.w);
        __nv_bfloat162 h2 = __floats2bfloat162_rn(v1.x, v1.y);
        __nv_bfloat162 h3 = __floats2bfloat162_rn(v1.z, v1.w);
        uint4 o;
        o.x = *(uint32_t*)&h0; o.y = *(uint32_t*)&h1;
        o.z = *(uint32_t*)&h2; o.w = *(uint32_t*)&h3;
        g_wh4[rowbase + lane] = o;
        return;
    }

    /* ---- pick + worklist part ---- */
    int i = (blockIdx.x - NORMG) * blockDim.x + threadIdx.x;
    if (i >= BLP) return;

    if (i < 128) {
        int rt = i >> 3, bq = i & 7;
        int nr[BB];
#pragma unroll
        for (int bb = 0; bb < BB; bb++) nr[bb] = (g_K[bb] + 63) >> 6;
        if (rt < nr[bq]) {
            int cpre = 0;
#pragma unroll
            for (int rp = 0; rp < 16; rp++)
                if (rp < rt)
#pragma unroll
                    for (int bb = 0; bb < BB; bb++) cpre += (rp < nr[bb]);
            int within = 0;
#pragma unroll
            for (int bb = 0; bb < BB; bb++)
                if (bb < bq) within += (rt < nr[bb]);
            int pos0 = LL * (cpre + within);
#pragma unroll
            for (int l = 0; l < LL; l++)
                g_wl[pos0 + l] = (bq << 16) | (l << 8) | rt;
        }
        if (i == 0) {
            int tot = 0;
#pragma unroll
            for (int bb = 0; bb < BB; bb++) tot += nr[bb];
            g_nwork = LL * tot;
        }
    }

    int b = i / (LL * PP); int rem = i % (LL * PP);
    int l = rem / PP; int p = rem % PP;
    int k = g_orig2comp[b * PP + p];
    if (k < 0) return;
    int pc = g_poscnt_orig[b * PP + p];
    int target;
    if (pc > 0) {
        uint32_t x0 = 0u, x1 = (uint32_t)i;
        threefry_0_42(x0, x1);
        uint32_t bits = x0 ^ x1;
        float u = __uint_as_float((bits >> 9) | 0x3F800000u) - 1.0f;
        int r = (int)floorf(u * (float)pc);
        if (r > pc - 1) r = pc - 1;
        if (r < 0) r = 0;
        int lab = label[b * PP + p];
        int start = g_grpoff[b * (NLABEL + 1) + lab];
        int j = g_posingrp[b * PP + p];
        int sel = (r < j) ? r : (r + 1);
        target = g_grpitems[b * PP + start + sel];
    } else {
        target = p;   /* diag fallback */
    }
    g_pospick[(b * LL + l) * PP + k] = g_orig2comp[b * PP + target];
}

/* ------------- K5: symmetric persistent HMMA GEMM + FUSED final reduction -------
 * Greedy items; after the worklist drains, all 296 co-resident CTAs pass a
 * quasi grid barrier (arrival counter + spin) and cooperatively compute the
 * per-row loss + per-(b,l) means + final scalar — no extra kernel launch.
 */
#define BN_T 128
#define A_OFF    0         /* 8 x 4096 = 32768 */
#define B_OFF    32768     /* 4 bufs x 16384 = 65536 */
#define SLAB_OFF 98304     /* 3 slots x (512 lab + 512 pick + 512 last) = 4608 */
#define SRED_OFF 102912    /* 1024 */
#define SWP_OFF  103936    /* 16 */
#define SMEM_DYN (103952 + 1024)
#define NPERSIST 296

__device__ __forceinline__ void prefetch_pair(int stp, int nstp, int ct0,
                                              const __nv_bfloat16* __restrict__ W,
                                              const int* __restrict__ clab,
                                              const int* __restrict__ pickp,
                                              const int* __restrict__ lastp,
                                              uint32_t sb, int tid) {
    if (stp < nstp) {
        uint32_t bbase = sb + B_OFF + (uint32_t)(stp & 3) * 16384u;
#pragma unroll
        for (int h = 0; h < 2; h++) {
            int gsub = 2 * stp + h;
            int tix = gsub >> 3, s2 = gsub & 7;
            int colbase = (ct0 + tix) * 128;
#pragma unroll
            for (int j = 0; j < 2; j++) {
                int id = j * 256 + tid;
                int r = id >> 2, c = id & 3;
                const void* src = W + (size_t)(colbase + r) * DD + s2 * 32 + c * 8;
                uint32_t dst = bbase + (uint32_t)(h * 8192 + r * 64)
                             + (uint32_t)((c ^ ((r >> 1) & 3)) << 4);
                cp16(dst, src);
            }
            if (s2 == 0 && tid < 96) {
                int a = tid >> 5, t32 = tid & 31;
                const int* src = (a == 0) ? (clab + colbase + t32 * 4)
                              : (a == 1) ? (pickp + colbase + t32 * 4)
                                         : (lastp + colbase + t32 * 4);
                cp16(sb + SLAB_OFF + (uint32_t)((tix % 3) * 1536 + a * 512 + t32 * 16), src);
            }
        }
    }
    CP_COMMIT();
}

__global__ void __launch_bounds__(256, 2) k_lse_hmma(float* __restrict__ out) {
    extern __shared__ char dsm[];
    uint32_t sraw = smem_u32(dsm);
    uint32_t sb = (sraw + 1023u) & ~1023u;
    char* amem = dsm + (sb - sraw);

    int tid = threadIdx.x;
    int wid = tid >> 5, lane = tid & 31;
    int mwarp = wid >> 2, nwarp = wid & 3;
    int g = lane >> 2, tg = lane & 3;
    int grp = lane >> 3, li = lane & 7;

    int nwork = g_nwork;
    int* s_wp = (int*)(amem + SWP_OFF);

    /* item-independent fragment smem addresses */
    uint32_t rowA = (uint32_t)(mwarp * 32 + (grp & 1) * 8 + li);
    uint32_t cA = (uint32_t)(grp >> 1);
    uint32_t addrA0 = sb + A_OFF + rowA * 64u + ((cA ^ ((rowA >> 1) & 3u)) << 4);
    uint32_t rowB = (uint32_t)(nwarp * 32 + (grp >> 1) * 8 + li);
    uint32_t cB = (uint32_t)(grp & 1);
    uint32_t addrB0 = rowB * 64u + ((cB ^ ((rowB >> 1) & 3u)) << 4);

    while (true) {
        __syncthreads();
        if (tid == 0) s_wp[0] = atomicAdd(&g_witem, 1);
        __syncthreads();
        int w = s_wp[0];
        if (w >= nwork) break;

        int wv = g_wl[w];
        int b = wv >> 16, l = (wv >> 8) & 255, rt = wv & 255;
        int K = g_K[b];
        int row0 = rt * 64;
        int bl = b * LL + l;
        const __nv_bfloat16* W = (const __nv_bfloat16*)g_wh4 + (size_t)bl * PP * DD;
        const int* clab = g_clab + b * PP;
        const int* pickp = g_pospick + (size_t)bl * PP;
        const int* lastp = g_lastcomp + b * PP;

        int ct0 = rt >> 1;
        int nct = (K + 127) >> 7;
        int nstp = (nct - ct0) * 4;

        /* per-thread row state (4 rows: mt in {0,1}, e in {0,1}) */
        int rloc[4], rlab[4], pick[4], last[4];
        float ssum[4];
#pragma unroll
        for (int i = 0; i < 4; i++) {
            int mt = i >> 1, e = i & 1;
            rloc[i] = mwarp * 32 + mt * 16 + g + 8 * e;
            int grow = row0 + rloc[i];
            rlab[i] = clab[grow];
            pick[i] = pickp[grow];
            last[i] = lastp[grow];
            ssum[i] = 0.f;
        }

        /* prologue: A (64x256) bundled with stage 0; stages 1, 2 */
#pragma unroll
        for (int j = 0; j < 8; j++) {
            int id = j * 256 + tid;
            int s = id >> 8, rem2 = id & 255;
            int r = rem2 >> 2, c = rem2 & 3;
            const void* src = W + (size_t)(row0 + r) * DD + s * 32 + c * 8;
            uint32_t dst = sb + A_OFF + (uint32_t)(s * 4096 + r * 64)
                         + (uint32_t)((c ^ ((r >> 1) & 3)) << 4);
            cp16(dst, src);
        }
        prefetch_pair(0, nstp, ct0, W, clab, pickp, lastp, sb, tid);
        prefetch_pair(1, nstp, ct0, W, clab, pickp, lastp, sb, tid);
        prefetch_pair(2, nstp, ct0, W, clab, pickp, lastp, sb, tid);

        float acc[2][4][4];
#pragma unroll
        for (int mt = 0; mt < 2; mt++)
#pragma unroll
            for (int nt = 0; nt < 4; nt++)
#pragma unroll
                for (int q = 0; q < 4; q++) acc[mt][nt][q] = 0.f;

#pragma unroll 1
        for (int st = 0; st < nstp; st++) {
            CP_WAIT2();
            __syncthreads();
            prefetch_pair(st + 3, nstp, ct0, W, clab, pickp, lastp, sb, tid);

            uint32_t bbase = sb + B_OFF + (uint32_t)(st & 3) * 16384u;
#pragma unroll
            for (int h = 0; h < 2; h++) {
                int s2 = (2 * st + h) & 7;
                uint32_t aAddr = addrA0 + (uint32_t)(s2 * 4096);
                uint32_t bAddr = bbase + (uint32_t)(h * 8192) + addrB0;
#pragma unroll
                for (int kk = 0; kk < 2; kk++) {
                    uint32_t kx = (uint32_t)(kk * 32);
                    uint32_t a0[4], a1[4], bf[8];
                    LDSM4(a0[0], a0[1], a0[2], a0[3], aAddr ^ kx);
                    LDSM4(a1[0], a1[1], a1[2], a1[3], (aAddr + 1024u) ^ kx);
                    LDSM4(bf[0], bf[1], bf[2], bf[3], bAddr ^ kx);
                    LDSM4(bf[4], bf[5], bf[6], bf[7], (bAddr + 1024u) ^ kx);
#pragma unroll
                    for (int nt = 0; nt < 4; nt++) {
                        mma_bf16(acc[0][nt][0], acc[0][nt][1], acc[0][nt][2], acc[0][nt][3],
                                 a0[0], a0[1], a0[2], a0[3], bf[nt * 2], bf[nt * 2 + 1]);
                        mma_bf16(acc[1][nt][0], acc[1][nt][1], acc[1][nt][2], acc[1][nt][3],
                                 a1[0], a1[1], a1[2], a1[3], bf[nt * 2], bf[nt * 2 + 1]);
                    }
                }
            }

            if ((st & 3) == 3) {
                /* ---- epilogue for tile tix ---- */
                int tix = st >> 2;
                int ct = ct0 + tix;
                int col0 = ct * BN_T;
                bool isdual = (tix > 0);
                const int* slotp = (const int*)(amem + SLAB_OFF + (tix % 3) * 1536);
                int cls[8], spc[8], slc[8];
#pragma unroll
                for (int nt = 0; nt < 4; nt++)
#pragma unroll
                    for (int q = 0; q < 2; q++) {
                        int ci = nwarp * 32 + nt * 8 + tg * 2 + q;
                        cls[nt * 2 + q] = slotp[ci];
                        spc[nt * 2 + q] = slotp[128 + ci];
                        slc[nt * 2 + q] = slotp[256 + ci];
                    }

                float colsum[8];
#pragma unroll
                for (int j = 0; j < 8; j++) colsum[j] = 0.f;

                int cgb = col0 + nwarp * 32 + tg * 2;
#pragma unroll
                for (int i = 0; i < 4; i++) {
                    int mt = i >> 1, e = i & 1;
                    int lr = rlab[i];
                    int cr = row0 + rloc[i];
                    bool rowok = (lr >= 0);
                    size_t o = (size_t)bl * PP + cr;
                    float s4 = 0.f;
#pragma unroll
                    for (int nt = 0; nt < 4; nt++) {
                        float z0 = acc[mt][nt][e * 2 + 0];
                        float z1 = acc[mt][nt][e * 2 + 1];
                        int cg0 = cgb + nt * 8;
                        unsigned dp = (unsigned)(pick[i] - cg0);
                        unsigned dl = (unsigned)(last[i] - cg0);
                        if (dp < 2u) g_zp[o] = (dp ? z1 : z0) * M0C;
                        if (dl < 2u) g_zl[o] = (dl ? z1 : z0) * M0C;
#pragma unroll
                        for (int q = 0; q < 2; q++) {
                            float av = q ? z1 : z0;
                            int j = nt * 2 + q;
                            int cl = cls[j];
                            bool isneg = rowok && (cl >= 0) && (cl != lr);
                            float y = fmaf(av, C2LOG, -C2LOG);
                            y = isneg ? y : -110.0f;
                            float t = y + 12582912.0f;      /* RN magic */
                            float nf = t - 12582912.0f;
                            float f = y - nf;
                            float p = 9.6181291076e-3f;
                            p = fmaf(p, f, 5.5504108664e-2f);
                            p = fmaf(p, f, 2.4022650695e-1f);
                            p = fmaf(p, f, 6.9314718056e-1f);
                            p = fmaf(p, f, 1.0f);
                            int rbits = __float_as_int(p) + (__float_as_int(t) << 23);
                            float es = __int_as_float(rbits);
                            s4 += es;
                            if (isdual) {
                                colsum[j] += es;
                                /* transposed zp/zl: pick/last of col == this row */
                                if (spc[j] == cr)
                                    g_zp[(size_t)bl * PP + col0 + nwarp * 32 + nt * 8 + tg * 2 + q] = av * M0C;
                                if (slc[j] == cr)
                                    g_zl[(size_t)bl * PP + col0 + nwarp * 32 + nt * 8 + tg * 2 + q] = av * M0C;
                            }
                        }
                    }
                    ssum[i] += s4;
                }

                if (isdual) {
                    /* col-sum reduce over the 8 row-lanes (g bits), atomics from lanes 0-3 */
#pragma unroll
                    for (int j = 0; j < 8; j++) {
                        float s = colsum[j];
                        s += __shfl_xor_sync(0xffffffffu, s, 4);
                        s += __shfl_xor_sync(0xffffffffu, s, 8);
                        s += __shfl_xor_sync(0xffffffffu, s, 16);
                        if (lane < 4)
                            atomicAdd(&g_S[(size_t)bl * PP + col0 + nwarp * 32
                                           + (j >> 1) * 8 + lane * 2 + (j & 1)], s);
                    }
                }
#pragma unroll
                for (int mt = 0; mt < 2; mt++)
#pragma unroll
                    for (int nt = 0; nt < 4; nt++)
#pragma unroll
                        for (int q = 0; q < 4; q++) acc[mt][nt][q] = 0.f;
            }
        }

        /* ---- row-S writeback: reduce tg lanes, then across the 4 nwarp warps ---- */
        float* sred = (float*)(amem + SRED_OFF);   /* 8 warps x 32 rows */
#pragma unroll
        for (int i = 0; i < 4; i++) {
            float s = ssum[i];
            s += __shfl_xor_sync(0xffffffffu, s, 1);
            s += __shfl_xor_sync(0xffffffffu, s, 2);
            if (tg == 0) {
                int mt = i >> 1, e = i & 1;
                sred[wid * 32 + mt * 16 + g + 8 * e] = s;
            }
        }
        __syncthreads();
        if (tid < 64) {
            int mw = tid >> 5, r32 = tid & 31;
            float s = sred[(mw * 4 + 0) * 32 + r32] + sred[(mw * 4 + 1) * 32 + r32]
                    + sred[(mw * 4 + 2) * 32 + r32] + sred[(mw * 4 + 3) * 32 + r32];
            int grow = row0 + tid;
            if (grow < K)
                atomicAdd(&g_S[(size_t)bl * PP + grow], s);
        }
    }

    /* ======== fused final reduction (all 296 CTAs co-resident) ======== */
    if (tid == 0) {
        __threadfence();                       /* release S/zp/zl writes */
        atomicAdd(&g_fin, 1);
        volatile int* fp = (volatile int*)&g_fin;
        while (*fp < NPERSIST) __nanosleep(64);
    }
    __syncthreads();
    __threadfence();                           /* acquire */

    int row = blockIdx.x * 256 + tid;
    float v = 0.f;
    int bl2 = row >> 10;
    int b2 = bl2 / LL;
    if (row < BLP) {
        int k = row & 1023;
        int K2 = g_K[b2];
        if (k < K2) {
            float zp = g_zp[row], S = g_S[row];
            int negc = g_cnegcnt[b2 * PP + k];
            float ez = __expf(zp - M0C);
            float padterm = 0.f;
            if (negc > 0) {
                int padi = K2 - 1 - negc; if (padi < 0) padi = 0;
                padterm = (float)padi * __expf(g_zl[row] - M0C);
            } else {
                S = 0.f;
            }
            v = M0C + __logf(ez + S + padterm) - zp;
        }
    }
    float* red = (float*)(amem + SRED_OFF);
    red[tid] = v; __syncthreads();
    for (int s = 128; s; s >>= 1) {
        if (tid < s) red[tid] += red[tid + s];
        __syncthreads();
    }
    if (tid == 0) {
        if (row < BLP) {
            int K2 = g_K[b2];
            int Kd = (K2 > 1) ? K2 : 1;
            float contrib = g_gate[b2] ? (red[0] / (float)Kd) : 0.f;
            atomicAdd(&g_partial[bl2], contrib);
        }
        __threadfence();
        int d = atomicAdd(&g_done, 1);
        if (d == NPERSIST - 1) {
            __threadfence();
            float s = 0.f;
            for (int i = 0; i < BB * LL; i++) s += g_partial[i];
            out[0] = s;
        }
    }
}

/* ------------------- launch ------------------- */
extern "C" void kernel_launch(void* const* d_in, const int* in_sizes, int n_in,
                              void* d_out, int out_size) {
    const float* meta = (const float*)d_in[0];
    const int* thing = (const int*)d_in[1];
    const int* label = (const int*)d_in[2];
    float* out = (float*)d_out;

    cudaFuncSetAttribute(k_lse_hmma, cudaFuncAttributeMaxDynamicSharedMemorySize, SMEM_DYN);

    k_meta<<<BB, 256>>>(thing, label);
    k_normpick<<<NORMG + (BLP + 255) / 256, 256>>>(meta, label);
    k_lse_hmma<<<NPERSIST, 256, SMEM_DYN>>>(out);
}

// round 17
// speedup vs baseline: 1.0628x; 1.0628x over previous
#include <cuda_runtime.h>
#include <cuda_bf16.h>
#include <stdint.h>

#define BB 8
#define NN 128
#define TT 8
#define LL 6
#define PP 1024
#define DD 256
#define NLABEL 40
#define BLP (BB*LL*PP)      /* 49152 */
#define M0C (1.0f/0.07f)
#define C2LOG (20.609929155556620f)   /* M0C * log2(e) */

/* ------------- device scratch (no allocations allowed) ------------- */
__device__ uint4 g_wh4[(size_t)BB*LL*PP*DD/8];  /* bf16 normalized rows */
__device__ int   g_K[BB];
__device__ int   g_gate[BB];
__device__ int   g_comp2orig[BB*PP];
__device__ int   g_orig2comp[BB*PP];
__device__ __align__(16) int g_clab[BB*PP];     /* labels by compact idx, pad=-1 */
__device__ int   g_cnegcnt[BB*PP];
__device__ int   g_poscnt_orig[BB*PP];
__device__ int   g_posingrp[BB*PP];
__device__ int   g_grpoff[BB*(NLABEL+1)];
__device__ int   g_grpitems[BB*PP];
__device__ __align__(16) int g_lastcomp[BB*PP]; /* compact last-neg idx, pad=-1 */
__device__ __align__(16) int g_pospick[BLP];    /* compact pick idx, pad=-1 */
__device__ float g_zp[BLP];
__device__ float g_zl[BLP];
__device__ float g_S[BLP];
__device__ float g_partial[BB*LL];
__device__ int   g_wl[BB*LL*16];
__device__ int   g_nwork;
__device__ int   g_witem;
__device__ int   g_done;

/* ------------------- helpers ------------------- */
__device__ __forceinline__ uint32_t rotl32(uint32_t x, int r) {
    return (x << r) | (x >> (32 - r));
}

/* JAX threefry2x32 with key = jax.random.key(42) -> (0, 42) */
__device__ __forceinline__ void threefry_0_42(uint32_t& x0, uint32_t& x1) {
    const uint32_t ks0 = 0u, ks1 = 42u, ks2 = 0u ^ 42u ^ 0x1BD11BDAu;
    x0 += ks0; x1 += ks1;
#define TF_RND(r) { x0 += x1; x1 = rotl32(x1, r); x1 ^= x0; }
    TF_RND(13) TF_RND(15) TF_RND(26) TF_RND(6)  x0 += ks1; x1 += ks2 + 1u;
    TF_RND(17) TF_RND(29) TF_RND(16) TF_RND(24) x0 += ks2; x1 += ks0 + 2u;
    TF_RND(13) TF_RND(15) TF_RND(26) TF_RND(6)  x0 += ks0; x1 += ks1 + 3u;
    TF_RND(17) TF_RND(29) TF_RND(16) TF_RND(24) x0 += ks1; x1 += ks2 + 4u;
    TF_RND(13) TF_RND(15) TF_RND(26) TF_RND(6)  x0 += ks2; x1 += ks0 + 5u;
#undef TF_RND
}

__device__ __forceinline__ void mma_bf16(float& d0, float& d1, float& d2, float& d3,
                                         uint32_t a0, uint32_t a1, uint32_t a2, uint32_t a3,
                                         uint32_t b0, uint32_t b1) {
    asm volatile(
        "mma.sync.aligned.m16n8k16.row.col.f32.bf16.bf16.f32 "
        "{%0,%1,%2,%3}, {%4,%5,%6,%7}, {%8,%9}, {%0,%1,%2,%3};"
        : "+f"(d0), "+f"(d1), "+f"(d2), "+f"(d3)
        : "r"(a0), "r"(a1), "r"(a2), "r"(a3), "r"(b0), "r"(b1));
}

#define LDSM4(r0, r1, r2, r3, addr) \
    asm volatile("ldmatrix.sync.aligned.m8n8.x4.shared.b16 {%0,%1,%2,%3}, [%4];" \
                 : "=r"(r0), "=r"(r1), "=r"(r2), "=r"(r3) : "r"(addr))

__device__ __forceinline__ void cp16(uint32_t dst, const void* src) {
    asm volatile("cp.async.cg.shared.global [%0], [%1], 16;" :: "r"(dst), "l"(src) : "memory");
}
#define CP_COMMIT() asm volatile("cp.async.commit_group;" ::: "memory")
#define CP_WAIT2()  asm volatile("cp.async.wait_group 2;" ::: "memory")

__device__ __forceinline__ uint32_t smem_u32(const void* p) {
    uint32_t a;
    asm("{ .reg .u64 t; cvta.to.shared.u64 t, %1; cvt.u32.u64 %0, t; }" : "=r"(a) : "l"(p));
    return a;
}

/* ------------------- K1: per-batch metadata, one-shot 1024-thread scan -------------------
 * One thread per position. Compact rank via ballot; within-label rank via
 * match_any; cross-warp prefixes via 32-entry smem hists. lastcomp computed
 * algebraically: crank(L1) = K-1; crank(L2) captured during the scan.
 */
__global__ void __launch_bounds__(1024) k_meta(const int* __restrict__ thing,
                                               const int* __restrict__ label) {
    int b = blockIdx.x, tid = threadIdx.x;
    int wid = tid >> 5, lane = tid & 31;
    __shared__ int s_cnt[NLABEL];
    __shared__ int s_off[NLABEL + 1];
    __shared__ int s_whist[32][NLABEL];
    __shared__ int s_wvalid[32];
    __shared__ int s_L1, s_L2, s_labL1, s_gate, s_K, s_crkL2;
    if (tid < NLABEL) s_cnt[tid] = 0;
    for (int i = tid; i < 32 * NLABEL; i += 1024) ((int*)s_whist)[i] = 0;
    if (tid == 0) { s_L1 = -1; s_L2 = -1; s_labL1 = -1; s_gate = 0; s_crkL2 = -1; }
    if (b == 0 && tid == 0) { g_done = 0; g_witem = 0; }
    if (tid < LL) g_partial[b * LL + tid] = 0.f;
    __syncthreads();

    int p = tid;
    int v = thing[b * PP + p];
    int lab = label[b * PP + p];
    bool valid = (v != 0);
    int pk = valid ? (lab + 1) : 0;
    if (valid) { atomicAdd(&s_cnt[lab], 1); atomicMax(&s_L1, p); }
    if (tid < NN) {
        int ss = 0;
#pragma unroll
        for (int t = 0; t < TT; t++) ss += thing[(b * NN + tid) * TT + t];
        if (ss > 0) atomicAdd(&s_gate, 1);
    }
    __syncthreads();
    if (tid == 0) {
        int acc = 0;
        for (int vv = 0; vv < NLABEL; vv++) { s_off[vv] = acc; acc += s_cnt[vv]; }
        s_off[NLABEL] = acc; s_K = acc;
        g_K[b] = acc;
        g_gate[b] = (s_gate >= 2) ? 1 : 0;
    }
    __syncthreads();
    if (valid && p == s_L1) s_labL1 = lab;
    __syncthreads();
    int labL1 = s_labL1;
    if (valid && lab != labL1) atomicMax(&s_L2, p);

    /* warp scan (independent of s_L2; barrier after covers both) */
    uint32_t lmlt = (1u << lane) - 1u;
    uint32_t vb = __ballot_sync(0xffffffffu, valid);
    uint32_t mm = __match_any_sync(0xffffffffu, pk);
    int crw = __popc(vb & lmlt);
    int grw = __popc(mm & lmlt);
    int leader = __ffs(mm) - 1;
    if (valid && lane == leader) s_whist[wid][lab] = __popc(mm);
    if (lane == 0) s_wvalid[wid] = __popc(vb);
    __syncthreads();

    int K = s_K, L2 = s_L2;
    int crank = -1, grank = 0;
    if (valid) {
        int crk = crw, grk = grw;
        for (int w2 = 0; w2 < wid; w2++) {
            crk += s_wvalid[w2];
            grk += s_whist[w2][lab];
        }
        crank = crk; grank = grk;
        if (p == L2) s_crkL2 = crank;
    }
    __syncthreads();
    int crkL2 = s_crkL2;

    if (valid) {
        g_orig2comp[b * PP + p] = crank;
        g_comp2orig[b * PP + crank] = p;
        g_clab[b * PP + crank] = lab;
        int cl = s_cnt[lab];
        g_poscnt_orig[b * PP + p] = cl - 1;
        g_cnegcnt[b * PP + crank] = K - cl;
        g_posingrp[b * PP + p] = grank;
        g_grpitems[b * PP + s_off[lab] + grank] = p;
        g_lastcomp[b * PP + crank] = (lab != labL1) ? (K - 1) : crkL2;
    } else {
        g_orig2comp[b * PP + p] = -1;
    }
    if (tid <= NLABEL) g_grpoff[b * (NLABEL + 1) + tid] = s_off[tid];
    if (tid >= K) {            /* pad region, keyed by compact idx */
        g_lastcomp[b * PP + tid] = -1;
        g_clab[b * PP + tid] = -1;
        g_cnegcnt[b * PP + tid] = 0;
    }
    /* zero S + pad picks */
    for (int idx = tid; idx < LL * PP; idx += 1024) {
        int l = idx >> 10, k = idx & 1023;
        g_S[((size_t)b * LL + l) * PP + k] = 0.f;
        if (k >= K) g_pospick[(b * LL + l) * PP + k] = -1;
    }
}

/* ------------- K2: fused norm (blocks < NORMG) + pick/worklist (blocks >= NORMG) ------------- */
#define NORMG 6144
__global__ void k_normpick(const float* __restrict__ meta, const int* __restrict__ label) {
    if (blockIdx.x < NORMG) {
        int w = (blockIdx.x * blockDim.x + threadIdx.x) >> 5;
        int lane = threadIdx.x & 31;
        int b = w / (LL * PP); int rem = w % (LL * PP);
        int l = rem / PP; int k = rem % PP;
        int K = g_K[b];
        int PPpad = ((K + 127) >> 7) << 7;
        if (k >= PPpad) return;
        size_t rowbase = ((size_t)(b * LL + l) * PP + k) * (DD / 8);
        if (k >= K) {
            g_wh4[rowbase + lane] = make_uint4(0u, 0u, 0u, 0u);
            return;
        }
        int p = g_comp2orig[b * PP + k];
        int n = p >> 3, t = p & 7;
        const float* src = meta + ((((size_t)b * NN + n) * TT + t) * LL + l) * DD;
        float4 v0 = ((const float4*)src)[lane * 2];
        float4 v1 = ((const float4*)src)[lane * 2 + 1];
        float ss = v0.x*v0.x + v0.y*v0.y + v0.z*v0.z + v0.w*v0.w
                 + v1.x*v1.x + v1.y*v1.y + v1.z*v1.z + v1.w*v1.w;
        for (int off = 16; off; off >>= 1) ss += __shfl_xor_sync(0xffffffffu, ss, off);
        float inv = 1.0f / fmaxf(sqrtf(ss), 1e-12f);
        v0.x*=inv; v0.y*=inv; v0.z*=inv; v0.w*=inv;
        v1.x*=inv; v1.y*=inv; v1.z*=inv; v1.w*=inv;
        __nv_bfloat162 h0 = __floats2bfloat162_rn(v0.x, v0.y);
        __nv_bfloat162 h1 = __floats2bfloat162_rn(v0.z, v0.w);
        __nv_bfloat162 h2 = __floats2bfloat162_rn(v1.x, v1.y);
        __nv_bfloat162 h3 = __floats2bfloat162_rn(v1.z, v1.w);
        uint4 o;
        o.x = *(uint32_t*)&h0; o.y = *(uint32_t*)&h1;
        o.z = *(uint32_t*)&h2; o.w = *(uint32_t*)&h3;
        g_wh4[rowbase + lane] = o;
        return;
    }

    /* ---- pick + worklist part ---- */
    int i = (blockIdx.x - NORMG) * blockDim.x + threadIdx.x;
    if (i >= BLP) return;

    if (i < 128) {
        int rt = i >> 3, bq = i & 7;
        int nr[BB];
#pragma unroll
        for (int bb = 0; bb < BB; bb++) nr[bb] = (g_K[bb] + 63) >> 6;
        if (rt < nr[bq]) {
            int cpre = 0;
#pragma unroll
            for (int rp = 0; rp < 16; rp++)
                if (rp < rt)
#pragma unroll
                    for (int bb = 0; bb < BB; bb++) cpre += (rp < nr[bb]);
            int within = 0;
#pragma unroll
            for (int bb = 0; bb < BB; bb++)
                if (bb < bq) within += (rt < nr[bb]);
            int pos0 = LL * (cpre + within);
#pragma unroll
            for (int l = 0; l < LL; l++)
                g_wl[pos0 + l] = (bq << 16) | (l << 8) | rt;
        }
        if (i == 0) {
            int tot = 0;
#pragma unroll
            for (int bb = 0; bb < BB; bb++) tot += nr[bb];
            g_nwork = LL * tot;
        }
    }

    int b = i / (LL * PP); int rem = i % (LL * PP);
    int l = rem / PP; int p = rem % PP;
    int k = g_orig2comp[b * PP + p];
    if (k < 0) return;
    int pc = g_poscnt_orig[b * PP + p];
    int target;
    if (pc > 0) {
        uint32_t x0 = 0u, x1 = (uint32_t)i;
        threefry_0_42(x0, x1);
        uint32_t bits = x0 ^ x1;
        float u = __uint_as_float((bits >> 9) | 0x3F800000u) - 1.0f;
        int r = (int)floorf(u * (float)pc);
        if (r > pc - 1) r = pc - 1;
        if (r < 0) r = 0;
        int lab = label[b * PP + p];
        int start = g_grpoff[b * (NLABEL + 1) + lab];
        int j = g_posingrp[b * PP + p];
        int sel = (r < j) ? r : (r + 1);
        target = g_grpitems[b * PP + start + sel];
    } else {
        target = p;   /* diag fallback */
    }
    g_pospick[(b * LL + l) * PP + k] = g_orig2comp[b * PP + target];
}

/* ------------- K5: symmetric persistent HMMA GEMM (greedy scheduling) ------------- */
#define BN_T 128
#define A_OFF    0         /* 8 x 4096 = 32768 */
#define B_OFF    32768     /* 4 bufs x 16384 = 65536 */
#define SLAB_OFF 98304     /* 3 slots x (512 lab + 512 pick + 512 last) = 4608 */
#define SRED_OFF 102912    /* 1024 */
#define SWP_OFF  103936    /* 16 */
#define SMEM_DYN (103952 + 1024)
#define NPERSIST 296

__device__ __forceinline__ void prefetch_pair(int stp, int nstp, int ct0,
                                              const __nv_bfloat16* __restrict__ W,
                                              const int* __restrict__ clab,
                                              const int* __restrict__ pickp,
                                              const int* __restrict__ lastp,
                                              uint32_t sb, int tid) {
    if (stp < nstp) {
        uint32_t bbase = sb + B_OFF + (uint32_t)(stp & 3) * 16384u;
#pragma unroll
        for (int h = 0; h < 2; h++) {
            int gsub = 2 * stp + h;
            int tix = gsub >> 3, s2 = gsub & 7;
            int colbase = (ct0 + tix) * 128;
#pragma unroll
            for (int j = 0; j < 2; j++) {
                int id = j * 256 + tid;
                int r = id >> 2, c = id & 3;
                const void* src = W + (size_t)(colbase + r) * DD + s2 * 32 + c * 8;
                uint32_t dst = bbase + (uint32_t)(h * 8192 + r * 64)
                             + (uint32_t)((c ^ ((r >> 1) & 3)) << 4);
                cp16(dst, src);
            }
            if (s2 == 0 && tid < 96) {
                int a = tid >> 5, t32 = tid & 31;
                const int* src = (a == 0) ? (clab + colbase + t32 * 4)
                              : (a == 1) ? (pickp + colbase + t32 * 4)
                                         : (lastp + colbase + t32 * 4);
                cp16(sb + SLAB_OFF + (uint32_t)((tix % 3) * 1536 + a * 512 + t32 * 16), src);
            }
        }
    }
    CP_COMMIT();
}

__global__ void __launch_bounds__(256, 2) k_lse_hmma() {
    extern __shared__ char dsm[];
    uint32_t sraw = smem_u32(dsm);
    uint32_t sb = (sraw + 1023u) & ~1023u;
    char* amem = dsm + (sb - sraw);

    int tid = threadIdx.x;
    int wid = tid >> 5, lane = tid & 31;
    int mwarp = wid >> 2, nwarp = wid & 3;
    int g = lane >> 2, tg = lane & 3;
    int grp = lane >> 3, li = lane & 7;

    int nwork = g_nwork;
    int* s_wp = (int*)(amem + SWP_OFF);

    /* item-independent fragment smem addresses */
    uint32_t rowA = (uint32_t)(mwarp * 32 + (grp & 1) * 8 + li);
    uint32_t cA = (uint32_t)(grp >> 1);
    uint32_t addrA0 = sb + A_OFF + rowA * 64u + ((cA ^ ((rowA >> 1) & 3u)) << 4);
    uint32_t rowB = (uint32_t)(nwarp * 32 + (grp >> 1) * 8 + li);
    uint32_t cB = (uint32_t)(grp & 1);
    uint32_t addrB0 = rowB * 64u + ((cB ^ ((rowB >> 1) & 3u)) << 4);

    while (true) {
        __syncthreads();
        if (tid == 0) s_wp[0] = atomicAdd(&g_witem, 1);
        __syncthreads();
        int w = s_wp[0];
        if (w >= nwork) break;

        int wv = g_wl[w];
        int b = wv >> 16, l = (wv >> 8) & 255, rt = wv & 255;
        int K = g_K[b];
        int row0 = rt * 64;
        int bl = b * LL + l;
        const __nv_bfloat16* W = (const __nv_bfloat16*)g_wh4 + (size_t)bl * PP * DD;
        const int* clab = g_clab + b * PP;
        const int* pickp = g_pospick + (size_t)bl * PP;
        const int* lastp = g_lastcomp + b * PP;

        int ct0 = rt >> 1;
        int nct = (K + 127) >> 7;
        int nstp = (nct - ct0) * 4;

        /* per-thread row state (4 rows: mt in {0,1}, e in {0,1}) */
        int rloc[4], rlab[4], pick[4], last[4];
        float ssum[4];
#pragma unroll
        for (int i = 0; i < 4; i++) {
            int mt = i >> 1, e = i & 1;
            rloc[i] = mwarp * 32 + mt * 16 + g + 8 * e;
            int grow = row0 + rloc[i];
            rlab[i] = clab[grow];
            pick[i] = pickp[grow];
            last[i] = lastp[grow];
            ssum[i] = 0.f;
        }

        /* prologue: A (64x256) bundled with stage 0; stages 1, 2 */
#pragma unroll
        for (int j = 0; j < 8; j++) {
            int id = j * 256 + tid;
            int s = id >> 8, rem2 = id & 255;
            int r = rem2 >> 2, c = rem2 & 3;
            const void* src = W + (size_t)(row0 + r) * DD + s * 32 + c * 8;
            uint32_t dst = sb + A_OFF + (uint32_t)(s * 4096 + r * 64)
                         + (uint32_t)((c ^ ((r >> 1) & 3)) << 4);
            cp16(dst, src);
        }
        prefetch_pair(0, nstp, ct0, W, clab, pickp, lastp, sb, tid);
        prefetch_pair(1, nstp, ct0, W, clab, pickp, lastp, sb, tid);
        prefetch_pair(2, nstp, ct0, W, clab, pickp, lastp, sb, tid);

        float acc[2][4][4];
#pragma unroll
        for (int mt = 0; mt < 2; mt++)
#pragma unroll
            for (int nt = 0; nt < 4; nt++)
#pragma unroll
                for (int q = 0; q < 4; q++) acc[mt][nt][q] = 0.f;

#pragma unroll 1
        for (int st = 0; st < nstp; st++) {
            CP_WAIT2();
            __syncthreads();
            prefetch_pair(st + 3, nstp, ct0, W, clab, pickp, lastp, sb, tid);

            uint32_t bbase = sb + B_OFF + (uint32_t)(st & 3) * 16384u;
#pragma unroll
            for (int h = 0; h < 2; h++) {
                int s2 = (2 * st + h) & 7;
                uint32_t aAddr = addrA0 + (uint32_t)(s2 * 4096);
                uint32_t bAddr = bbase + (uint32_t)(h * 8192) + addrB0;
#pragma unroll
                for (int kk = 0; kk < 2; kk++) {
                    uint32_t kx = (uint32_t)(kk * 32);
                    uint32_t a0[4], a1[4], bf[8];
                    LDSM4(a0[0], a0[1], a0[2], a0[3], aAddr ^ kx);
                    LDSM4(a1[0], a1[1], a1[2], a1[3], (aAddr + 1024u) ^ kx);
                    LDSM4(bf[0], bf[1], bf[2], bf[3], bAddr ^ kx);
                    LDSM4(bf[4], bf[5], bf[6], bf[7], (bAddr + 1024u) ^ kx);
#pragma unroll
                    for (int nt = 0; nt < 4; nt++) {
                        mma_bf16(acc[0][nt][0], acc[0][nt][1], acc[0][nt][2], acc[0][nt][3],
                                 a0[0], a0[1], a0[2], a0[3], bf[nt * 2], bf[nt * 2 + 1]);
                        mma_bf16(acc[1][nt][0], acc[1][nt][1], acc[1][nt][2], acc[1][nt][3],
                                 a1[0], a1[1], a1[2], a1[3], bf[nt * 2], bf[nt * 2 + 1]);
                    }
                }
            }

            if ((st & 3) == 3) {
                /* ---- epilogue for tile tix ---- */
                int tix = st >> 2;
                int ct = ct0 + tix;
                int col0 = ct * BN_T;
                bool isdual = (tix > 0);
                const int* slotp = (const int*)(amem + SLAB_OFF + (tix % 3) * 1536);
                int cls[8], spc[8], slc[8];
#pragma unroll
                for (int nt = 0; nt < 4; nt++)
#pragma unroll
                    for (int q = 0; q < 2; q++) {
                        int ci = nwarp * 32 + nt * 8 + tg * 2 + q;
                        cls[nt * 2 + q] = slotp[ci];
                        spc[nt * 2 + q] = slotp[128 + ci];
                        slc[nt * 2 + q] = slotp[256 + ci];
                    }

                float colsum[8];
#pragma unroll
                for (int j = 0; j < 8; j++) colsum[j] = 0.f;

                int cgb = col0 + nwarp * 32 + tg * 2;
#pragma unroll
                for (int i = 0; i < 4; i++) {
                    int mt = i >> 1, e = i & 1;
                    int lr = rlab[i];
                    int cr = row0 + rloc[i];
                    bool rowok = (lr >= 0);
                    size_t o = (size_t)bl * PP + cr;
                    float s4 = 0.f;
#pragma unroll
                    for (int nt = 0; nt < 4; nt++) {
                        float z0 = acc[mt][nt][e * 2 + 0];
                        float z1 = acc[mt][nt][e * 2 + 1];
                        int cg0 = cgb + nt * 8;
                        unsigned dp = (unsigned)(pick[i] - cg0);
                        unsigned dl = (unsigned)(last[i] - cg0);
                        if (dp < 2u) g_zp[o] = (dp ? z1 : z0) * M0C;
                        if (dl < 2u) g_zl[o] = (dl ? z1 : z0) * M0C;
#pragma unroll
                        for (int q = 0; q < 2; q++) {
                            float av = q ? z1 : z0;
                            int j = nt * 2 + q;
                            int cl = cls[j];
                            bool isneg = rowok && (cl >= 0) && (cl != lr);
                            float y = fmaf(av, C2LOG, -C2LOG);
                            y = isneg ? y : -110.0f;
                            float t = y + 12582912.0f;      /* RN magic */
                            float nf = t - 12582912.0f;
                            float f = y - nf;
                            float p = 9.6181291076e-3f;
                            p = fmaf(p, f, 5.5504108664e-2f);
                            p = fmaf(p, f, 2.4022650695e-1f);
                            p = fmaf(p, f, 6.9314718056e-1f);
                            p = fmaf(p, f, 1.0f);
                            int rbits = __float_as_int(p) + (__float_as_int(t) << 23);
                            float es = __int_as_float(rbits);
                            s4 += es;
                            if (isdual) {
                                colsum[j] += es;
                                /* transposed zp/zl: pick/last of col == this row */
                                if (spc[j] == cr)
                                    g_zp[(size_t)bl * PP + col0 + nwarp * 32 + nt * 8 + tg * 2 + q] = av * M0C;
                                if (slc[j] == cr)
                                    g_zl[(size_t)bl * PP + col0 + nwarp * 32 + nt * 8 + tg * 2 + q] = av * M0C;
                            }
                        }
                    }
                    ssum[i] += s4;
                }

                if (isdual) {
                    /* col-sum reduce over the 8 row-lanes (g bits), atomics from lanes 0-3 */
#pragma unroll
                    for (int j = 0; j < 8; j++) {
                        float s = colsum[j];
                        s += __shfl_xor_sync(0xffffffffu, s, 4);
                        s += __shfl_xor_sync(0xffffffffu, s, 8);
                        s += __shfl_xor_sync(0xffffffffu, s, 16);
                        if (lane < 4)
                            atomicAdd(&g_S[(size_t)bl * PP + col0 + nwarp * 32
                                           + (j >> 1) * 8 + lane * 2 + (j & 1)], s);
                    }
                }
#pragma unroll
                for (int mt = 0; mt < 2; mt++)
#pragma unroll
                    for (int nt = 0; nt < 4; nt++)
#pragma unroll
                        for (int q = 0; q < 4; q++) acc[mt][nt][q] = 0.f;
            }
        }

        /* ---- row-S writeback: reduce tg lanes, then across the 4 nwarp warps ---- */
        float* sred = (float*)(amem + SRED_OFF);   /* 8 warps x 32 rows */
#pragma unroll
        for (int i = 0; i < 4; i++) {
            float s = ssum[i];
            s += __shfl_xor_sync(0xffffffffu, s, 1);
            s += __shfl_xor_sync(0xffffffffu, s, 2);
            if (tg == 0) {
                int mt = i >> 1, e = i & 1;
                sred[wid * 32 + mt * 16 + g + 8 * e] = s;
            }
        }
        __syncthreads();
        if (tid < 64) {
            int mw = tid >> 5, r32 = tid & 31;
            float s = sred[(mw * 4 + 0) * 32 + r32] + sred[(mw * 4 + 1) * 32 + r32]
                    + sred[(mw * 4 + 2) * 32 + r32] + sred[(mw * 4 + 3) * 32 + r32];
            int grow = row0 + tid;
            if (grow < K)
                atomicAdd(&g_S[(size_t)bl * PP + grow], s);
        }
    }
}

/* ------------- K6: loss reduction, one thread per row (192 blocks) ------------- */
__global__ void k_final(float* __restrict__ out) {
    int tid = threadIdx.x;
    int row = blockIdx.x * 256 + tid;
    int bl = row >> 10, k = row & 1023;
    int b = bl / LL;
    int K = g_K[b];
    float v = 0.f;
    if (k < K) {
        float zp = g_zp[row], S = g_S[row];
        int negc = g_cnegcnt[b * PP + k];
        float ez = __expf(zp - M0C);
        float padterm = 0.f;
        if (negc > 0) {
            int padi = K - 1 - negc; if (padi < 0) padi = 0;
            padterm = (float)padi * __expf(g_zl[row] - M0C);
        } else {
            S = 0.f;
        }
        v = M0C + __logf(ez + S + padterm) - zp;
    }
    __shared__ float red[256];
    red[tid] = v; __syncthreads();
    for (int s = 128; s; s >>= 1) {
        if (tid < s) red[tid] += red[tid + s];
        __syncthreads();
    }
    if (tid == 0) {
        int Kd = (K > 1) ? K : 1;
        float contrib = g_gate[b] ? (red[0] / (float)Kd) : 0.f;
        atomicAdd(&g_partial[bl], contrib);
        __threadfence();
        int d = atomicAdd(&g_done, 1);
        if (d == (int)gridDim.x - 1) {
            __threadfence();
            float s = 0.f;
            for (int i = 0; i < BB * LL; i++) s += g_partial[i];
            out[0] = s;
        }
    }
}

/* ------------------- launch ------------------- */
extern "C" void kernel_launch(void* const* d_in, const int* in_sizes, int n_in,
                              void* d_out, int out_size) {
    const float* meta = (const float*)d_in[0];
    const int* thing = (const int*)d_in[1];
    const int* label = (const int*)d_in[2];
    float* out = (float*)d_out;

    cudaFuncSetAttribute(k_lse_hmma, cudaFuncAttributeMaxDynamicSharedMemorySize, SMEM_DYN);

    k_meta<<<BB, 1024>>>(thing, label);
    k_normpick<<<NORMG + (BLP + 255) / 256, 256>>>(meta, label);
    k_lse_hmma<<<NPERSIST, 256, SMEM_DYN>>>();
    k_final<<<BLP / 256, 256>>>(out);
}